// round 1
// baseline (speedup 1.0000x reference)
#include <cuda_runtime.h>

#define T_STEPS 730
#define N_GRID  10000
#define LENF    15
#define NEARZERO 1e-5f

// Scratch (static device globals: allocation-free per harness rules)
__device__ float g_qsim[T_STEPS * N_GRID];   // 29.2 MB mean-over-nmul runoff
__device__ float g_w[LENF * N_GRID];         // normalized UH weights [LENF, G]

// ---------------------------------------------------------------------------
// Kernel 1: sequential HBV scan. One thread per (grid cell, nmul component).
// Threads 2g and 2g+1 handle the two components of cell g; the per-step mean
// is combined with a shfl (off the recurrence critical path) and written by
// the even lane.
// ---------------------------------------------------------------------------
__global__ void __launch_bounds__(128) hbv_scan(
    const float* __restrict__ x_phy,     // [T, G, 3]
    const float* __restrict__ ac_all,    // [G]
    const float* __restrict__ pdy,       // [T, G, 2, 2]  (parBETA, parBETAET) x nmul
    const float* __restrict__ pstat)     // [G, 30]
{
    const int tid = blockIdx.x * blockDim.x + threadIdx.x;
    if (tid >= 2 * N_GRID) return;
    const int g = tid >> 1;
    const int m = tid & 1;

    // ---- static parameters (scaled to physical bounds), hoisted ----
    const float* ps = pstat + g * 30;
    const float parFC    = ps[0*2+m]  * 950.0f  + 50.0f;
    const float parK0    = ps[1*2+m]  * 0.85f   + 0.05f;
    const float parK1    = ps[2*2+m]  * 0.49f   + 0.01f;
    const float parK2    = ps[3*2+m]  * 0.199f  + 0.001f;
    const float parLP    = ps[4*2+m]  * 0.8f    + 0.2f;
    const float parPERC  = ps[5*2+m]  * 10.0f;
    const float parUZL   = ps[6*2+m]  * 100.0f;
    const float parTT    = ps[7*2+m]  * 5.0f    - 2.5f;
    const float parCFMAX = ps[8*2+m]  * 9.5f    + 0.5f;
    const float parCFR   = ps[9*2+m]  * 0.1f;
    const float parCWH   = ps[10*2+m] * 0.2f;
    const float parC     = ps[11*2+m];                 // [0,1]
    const float parRT    = ps[12*2+m] * 20.0f;
    const float parAC    = ps[13*2+m] * 2500.0f;

    const float Ac      = ac_all[g];
    const float invFC   = 1.0f / parFC;
    const float invLPFC = 1.0f / (parLP * parFC);
    const float crf     = parCFR * parCFMAX;
    // time-invariant groundwater-loss capacity
    const float gwcap   = parRT * fminf(fmaxf(1.0f - Ac / (parAC + NEARZERO), 0.0f), 1.0f);

    // ---- state ----
    float snowpack = 1e-3f, meltwater = 1e-3f, sm = 1e-3f, suz = 1e-3f, slz = 1e-3f;

    // ---- prefetched inputs for step 0 ----
    const float* x0 = x_phy + (long)g * 3;
    float P  = x0[0];
    float Ta = x0[1];
    float PE = x0[2];
    const float* d0 = pdy + (long)g * 4 + m;
    float b0 = d0[0];   // parBETA raw
    float b1 = d0[2];   // parBETAET raw

    for (int t = 0; t < T_STEPS; ++t) {
        // software prefetch next step's inputs (overlaps the dependency chain)
        const int tn = (t + 1 < T_STEPS) ? (t + 1) : t;
        const float* xn = x_phy + ((long)tn * N_GRID + g) * 3;
        const float nP  = xn[0];
        const float nTa = xn[1];
        const float nPE = xn[2];
        const float* dn = pdy + (long)tn * N_GRID * 4 + g * 4 + m;
        const float nb0 = dn[0];
        const float nb1 = dn[2];

        const float beta   = b0 * 5.0f + 1.0f;   // [1,6]
        const float betaet = b1 * 4.7f + 0.3f;   // [0.3,5]

        // --- snow bucket ---
        const float rain = (Ta >= parTT) ? P : 0.0f;
        const float snow = P - rain;
        snowpack += snow;
        float melt = fminf(fmaxf(parCFMAX * (Ta - parTT), 0.0f), snowpack);
        meltwater += melt;
        snowpack  -= melt;
        float refr = fminf(fmaxf(crf * (parTT - Ta), 0.0f), meltwater);
        snowpack  += refr;
        meltwater -= refr;
        float tosoil = fmaxf(meltwater - parCWH * snowpack, 0.0f);
        meltwater -= tosoil;

        // --- soil bucket ---
        float swet = fminf(__powf(sm * invFC, beta), 1.0f);       // clip(pow,0,1); pow>=0
        const float rpt = rain + tosoil;
        const float recharge = rpt * swet;
        sm += rpt - recharge;
        const float excess = fmaxf(sm - parFC, 0.0f);
        sm -= excess;
        const float efb = fminf(sm * invLPFC, 1.0f);              // clip(...,0,1), base>0
        const float ef  = __powf(efb, betaet);
        const float et  = fminf(sm, PE * ef);
        sm = fmaxf(sm - et, NEARZERO);
        const float cap = fminf(slz, parC * slz * (1.0f - fminf(sm * invFC, 1.0f)));
        sm  = fmaxf(sm + cap, NEARZERO);
        slz = fmaxf(slz - cap, NEARZERO);

        // --- groundwater buckets ---
        suz += recharge + excess;
        const float perc = fminf(suz, parPERC);
        suz -= perc;
        const float q0 = parK0 * fmaxf(suz - parUZL, 0.0f);
        suz -= q0;
        const float q1 = parK1 * suz;
        suz -= q1;
        slz += perc;
        const float gwl = fminf(slz, gwcap);
        slz -= gwl;
        const float q2 = parK2 * slz;
        slz -= q2;

        const float qt = q0 + q1 + q2;
        // mean over the two nmul components living in adjacent lanes
        const float qsum = qt + __shfl_xor_sync(0xffffffffu, qt, 1);
        if (m == 0) g_qsim[t * N_GRID + g] = 0.5f * qsum;

        P = nP; Ta = nTa; PE = nPE; b0 = nb0; b1 = nb1;
    }
}

// ---------------------------------------------------------------------------
// Kernel 2: normalized gamma unit-hydrograph weights.
// Normalization cancels exp(-lgamma(a)) * theta^(-a), so:
//   w[k] ∝ t_k^(a-1) * exp(-t_k/theta) = exp((a-1)*log t_k - t_k/theta)
// ---------------------------------------------------------------------------
__global__ void __launch_bounds__(128) hbv_weights(const float* __restrict__ pstat)
{
    const int g = blockIdx.x * blockDim.x + threadIdx.x;
    if (g >= N_GRID) return;
    const float a     = fmaxf(pstat[g * 30 + 28] * 2.9f, 0.0f) + 0.1f;
    const float theta = fmaxf(pstat[g * 30 + 29] * 6.5f, 0.0f) + 0.5f;
    const float am1    = a - 1.0f;
    const float invth  = 1.0f / theta;

    float w[LENF];
    float s = 0.0f;
    #pragma unroll
    for (int k = 0; k < LENF; ++k) {
        const float tk = (float)k + 0.5f;
        const float wk = expf(am1 * logf(tk) - tk * invth);
        w[k] = wk;
        s += wk;
    }
    const float invs = 1.0f / s;
    #pragma unroll
    for (int k = 0; k < LENF; ++k)
        g_w[k * N_GRID + g] = w[k] * invs;
}

// ---------------------------------------------------------------------------
// Kernel 3: causal 15-tap grouped convolution. Fully parallel over (t, g);
// Qsim (29 MB) fits in L2, so the 15 reads per output are mostly L2 hits.
// ---------------------------------------------------------------------------
__global__ void __launch_bounds__(256) hbv_route(float* __restrict__ out)
{
    const int g = blockIdx.x * blockDim.x + threadIdx.x;
    const int t = blockIdx.y;
    if (g >= N_GRID) return;

    float acc = 0.0f;
    #pragma unroll
    for (int k = 0; k < LENF; ++k) {
        const int ts = t - k;
        if (ts >= 0)
            acc += g_w[k * N_GRID + g] * g_qsim[ts * N_GRID + g];
    }
    out[t * N_GRID + g] = acc;
}

// ---------------------------------------------------------------------------
extern "C" void kernel_launch(void* const* d_in, const int* in_sizes, int n_in,
                              void* d_out, int out_size)
{
    const float* x_phy = (const float*)d_in[0];   // [730,10000,3]
    const float* ac    = (const float*)d_in[1];   // [10000]
    // d_in[2] = elev_all (unused by the model)
    const float* pdy   = (const float*)d_in[3];   // [730,10000,4]
    const float* pstat = (const float*)d_in[4];   // [10000,30]
    float* out = (float*)d_out;                   // [730,10000,1]

    hbv_scan<<<(2 * N_GRID + 127) / 128, 128>>>(x_phy, ac, pdy, pstat);
    hbv_weights<<<(N_GRID + 127) / 128, 128>>>(pstat);
    dim3 rgrid((N_GRID + 255) / 256, T_STEPS);
    hbv_route<<<rgrid, 256>>>(out);
}

// round 2
// speedup vs baseline: 2.3419x; 2.3419x over previous
#include <cuda_runtime.h>

#define T_STEPS 730
#define N_GRID  10000
#define LENF    15
#define NEARZERO 1e-5f
#define BLK 128
#define GPB 64            // grid cells per block (2 threads/cell)
#define DEPTH 8           // cp.async pipeline slots (lookahead = DEPTH-1 steps)

// ---------------------------------------------------------------------------
// 16-byte async global->shared copy (fire and forget; grouped via commit_group)
// ---------------------------------------------------------------------------
__device__ __forceinline__ void cp16(void* dst_smem, const void* src) {
    unsigned d = (unsigned)__cvta_generic_to_shared(dst_smem);
    asm volatile("cp.async.ca.shared.global [%0], [%1], 16;\n" :: "r"(d), "l"(src));
}

// Issue the async loads for timestep t into pipeline slot `slot`.
// Per stage: x_phy chunk = 64 cells * 3 floats = 768 B (48 x 16B),
//            pdy  chunk = 64 cells * 4 floats = 1024 B (64 x 16B). 112 ops total.
// Addresses are clamped in-bounds (only the tail block can run past the end;
// the clamped data lands in slots of inactive cells and is never used).
__device__ __forceinline__ void stage_load(
    int slot, int t, int gb,
    const float* __restrict__ x_phy, const float* __restrict__ pdy,
    float (*sx)[GPB * 3], float (*sd)[GPB * 4], int c)
{
    if (c < 112) {
        if (c < 48) {
            long idx = (long)t * (N_GRID * 3) + (long)gb * 3 + c * 4;
            const long lim = (long)T_STEPS * N_GRID * 3 - 4;
            if (idx > lim) idx = lim;
            cp16(&sx[slot][c * 4], x_phy + idx);
        } else {
            const int c2 = c - 48;
            long idx = (long)t * (N_GRID * 4) + (long)gb * 4 + c2 * 4;
            const long lim = (long)T_STEPS * N_GRID * 4 - 4;
            if (idx > lim) idx = lim;
            cp16(&sd[slot][c2 * 4], pdy + idx);
        }
    }
}

// ---------------------------------------------------------------------------
// Fully fused HBV: sequential scan + inline gamma-UH routing.
// One thread per (cell, nmul) pair; threads 2l / 2l+1 share a cell.
// ---------------------------------------------------------------------------
__global__ void __launch_bounds__(BLK) hbv_fused(
    const float* __restrict__ x_phy,   // [T, G, 3]
    const float* __restrict__ ac_all,  // [G]
    const float* __restrict__ pdy,     // [T, G, 2, 2]
    const float* __restrict__ pstat,   // [G, 30]
    float* __restrict__ out)           // [T, G]
{
    __shared__ float sx[DEPTH][GPB * 3];
    __shared__ float sd[DEPTH][GPB * 4];

    const int gb  = blockIdx.x * GPB;
    const int tid = blockIdx.x * BLK + threadIdx.x;
    const int lg  = threadIdx.x >> 1;
    const int m   = threadIdx.x & 1;
    const int g   = gb + lg;
    const bool active = (tid < 2 * N_GRID);
    const int gc  = (g < N_GRID) ? g : (N_GRID - 1);   // clamped for safe param loads

    // ---- static parameters (scaled), hoisted out of the time loop ----
    const float* ps = pstat + gc * 30;
    const float parFC    = ps[0*2+m]  * 950.0f  + 50.0f;
    const float parK0    = ps[1*2+m]  * 0.85f   + 0.05f;
    const float parK1    = ps[2*2+m]  * 0.49f   + 0.01f;
    const float parK2    = ps[3*2+m]  * 0.199f  + 0.001f;
    const float parLP    = ps[4*2+m]  * 0.8f    + 0.2f;
    const float parPERC  = ps[5*2+m]  * 10.0f;
    const float parUZL   = ps[6*2+m]  * 100.0f;
    const float parTT    = ps[7*2+m]  * 5.0f    - 2.5f;
    const float parCFMAX = ps[8*2+m]  * 9.5f    + 0.5f;
    const float parCFR   = ps[9*2+m]  * 0.1f;
    const float parCWH   = ps[10*2+m] * 0.2f;
    const float parC     = ps[11*2+m];
    const float parRT    = ps[12*2+m] * 20.0f;
    const float parAC    = ps[13*2+m] * 2500.0f;

    const float Ac      = ac_all[gc];
    const float invFC   = 1.0f / parFC;
    const float invLPFC = 1.0f / (parLP * parFC);
    const float crf     = parCFR * parCFMAX;
    const float gwcap   = parRT * fminf(fmaxf(1.0f - Ac / (parAC + NEARZERO), 0.0f), 1.0f);

    // ---- normalized gamma unit-hydrograph weights (lgamma/theta^-a cancel) ----
    // w[k] ∝ exp((a-1)*ln(k+0.5) - (k+0.5)/theta)
    const float a_r   = fmaxf(ps[28] * 2.9f, 0.0f) + 0.1f;
    const float th_r  = fmaxf(ps[29] * 6.5f, 0.0f) + 0.5f;
    const float am1   = a_r - 1.0f;
    const float ivt   = 1.0f / th_r;
    const float LOGTK[LENF] = {
        -0.69314718f, 0.40546511f, 0.91629073f, 1.25276297f, 1.50407740f,
         1.70474809f, 1.87180218f, 2.01490302f, 2.14006616f, 2.25129180f,
         2.35137526f, 2.44234704f, 2.52572864f, 2.60268969f, 2.67414865f };
    float w[LENF];
    float wsum = 0.0f;
    #pragma unroll
    for (int k = 0; k < LENF; ++k) {
        const float tk = (float)k + 0.5f;
        w[k] = __expf(am1 * LOGTK[k] - tk * ivt);
        wsum += w[k];
    }
    const float ivw = 1.0f / wsum;
    #pragma unroll
    for (int k = 0; k < LENF; ++k) w[k] *= ivw;

    // ---- state ----
    float snowpack = 1e-3f, meltwater = 1e-3f, sm = 1e-3f, suz = 1e-3f, slz = 1e-3f;
    float qh[LENF - 1];                 // routing history ring (q[t-1..t-14])
    #pragma unroll
    for (int k = 0; k < LENF - 1; ++k) qh[k] = 0.0f;

    // ---- cp.async pipeline prologue: stage data for steps 0..DEPTH-2 ----
    const int c = threadIdx.x;
    #pragma unroll
    for (int i = 0; i < DEPTH - 1; ++i) {
        stage_load(i, i, gb, x_phy, pdy, sx, sd, c);
        asm volatile("cp.async.commit_group;\n");
    }

    for (int t = 0; t < T_STEPS; ++t) {
        // ensure data(t) has landed (DEPTH-2 groups may remain in flight)
        asm volatile("cp.async.wait_group %0;\n" :: "n"(DEPTH - 2));
        __syncthreads();   // also guarantees everyone finished reading slot (t-1)%DEPTH

        const int slot = t & (DEPTH - 1);
        const float P  = sx[slot][lg * 3 + 0];
        const float Ta = sx[slot][lg * 3 + 1];
        const float PE = sx[slot][lg * 3 + 2];
        const float beta   = sd[slot][lg * 4 + m]     * 5.0f + 1.0f;   // [1,6]
        const float betaet = sd[slot][lg * 4 + 2 + m] * 4.7f + 0.3f;   // [0.3,5]

        // refill: data(t+DEPTH-1) into slot (t-1)%DEPTH (free after the barrier)
        const int tload = t + DEPTH - 1;
        if (tload < T_STEPS)
            stage_load(tload & (DEPTH - 1), tload, gb, x_phy, pdy, sx, sd, c);
        asm volatile("cp.async.commit_group;\n");

        // --- snow bucket ---
        const float rain = (Ta >= parTT) ? P : 0.0f;
        const float snow = P - rain;
        snowpack += snow;
        const float melt = fminf(fmaxf(parCFMAX * (Ta - parTT), 0.0f), snowpack);
        meltwater += melt;
        snowpack  -= melt;
        const float refr = fminf(fmaxf(crf * (parTT - Ta), 0.0f), meltwater);
        snowpack  += refr;
        meltwater -= refr;
        const float tosoil = fmaxf(meltwater - parCWH * snowpack, 0.0f);
        meltwater -= tosoil;

        // --- soil bucket ---
        const float swet = fminf(__powf(sm * invFC, beta), 1.0f);
        const float rpt  = rain + tosoil;
        const float recharge = rpt * swet;
        sm += rpt - recharge;
        const float excess = fmaxf(sm - parFC, 0.0f);
        sm -= excess;
        const float efb = fminf(sm * invLPFC, 1.0f);
        const float ef  = __powf(efb, betaet);
        const float et  = fminf(sm, PE * ef);
        sm = fmaxf(sm - et, NEARZERO);
        const float cap = fminf(slz, parC * slz * (1.0f - fminf(sm * invFC, 1.0f)));
        sm  = fmaxf(sm + cap, NEARZERO);
        slz = fmaxf(slz - cap, NEARZERO);

        // --- groundwater buckets ---
        suz += recharge + excess;
        const float perc = fminf(suz, parPERC);
        suz -= perc;
        const float q0 = parK0 * fmaxf(suz - parUZL, 0.0f);
        suz -= q0;
        const float q1 = parK1 * suz;
        suz -= q1;
        slz += perc;
        const float gwl = fminf(slz, gwcap);
        slz -= gwl;
        const float q2 = parK2 * slz;
        slz -= q2;

        const float qt = q0 + q1 + q2;
        // mean over the two nmul components (adjacent lanes)
        const float qs = 0.5f * (qt + __shfl_xor_sync(0xffffffffu, qt, 1));

        // --- inline gamma-UH routing: 15-tap causal conv on own history ---
        float flow = w[0] * qs;
        #pragma unroll
        for (int k = 1; k < LENF; ++k) flow += w[k] * qh[k - 1];
        #pragma unroll
        for (int k = LENF - 2; k >= 1; --k) qh[k] = qh[k - 1];
        qh[0] = qs;

        if (active && m == 0) out[t * N_GRID + g] = flow;
    }
}

// ---------------------------------------------------------------------------
extern "C" void kernel_launch(void* const* d_in, const int* in_sizes, int n_in,
                              void* d_out, int out_size)
{
    const float* x_phy = (const float*)d_in[0];   // [730,10000,3]
    const float* ac    = (const float*)d_in[1];   // [10000]
    // d_in[2] = elev_all (unused by the model)
    const float* pdy   = (const float*)d_in[3];   // [730,10000,4]
    const float* pstat = (const float*)d_in[4];   // [10000,30]
    float* out = (float*)d_out;                   // [730,10000,1]

    hbv_fused<<<(2 * N_GRID + BLK - 1) / BLK, BLK>>>(x_phy, ac, pdy, pstat, out);
}

// round 3
// speedup vs baseline: 3.7100x; 1.5842x over previous
#include <cuda_runtime.h>

#define T_STEPS 730
#define N_GRID  10000
#define LENF    15
#define NEARZERO 1e-5f
#define BLK   128
#define GPB   64            // grid cells per block (2 threads/cell)
#define CHUNK 7             // timesteps per cp.async stage (2 buffers => 14/superstep)
#define NCHUNKS 106         // ceil(742/7): covers 53 super-iterations of 14 steps

// Shared staging: [buf][step][data]
struct Smem {
    float sx[2][CHUNK][GPB * 3];   // P, Ta, PET
    float sd[2][CHUNK][GPB * 4];   // parBETA(m0,m1), parBETAET(m0,m1)
};

__device__ __forceinline__ void cp16(void* dst_smem, const void* src) {
    unsigned d = (unsigned)__cvta_generic_to_shared(dst_smem);
    asm volatile("cp.async.ca.shared.global [%0], [%1], 16;\n" :: "r"(d), "l"(src));
}

// Stage CHUNK timesteps (starting at t0) into buffer `buf`.
// Indices clamped to the tensor end; clamped data only lands in lanes that are
// inactive or in guarded-off timesteps and is never used for output.
__device__ __forceinline__ void stage(
    Smem& s, int buf, int t0, int gb,
    const float* __restrict__ x_phy, const float* __restrict__ pdy, int c)
{
    const long limx = (long)T_STEPS * N_GRID * 3 - 4;
    #pragma unroll
    for (int v = 0; v < 3; ++v) {                 // CHUNK*48 = 336 vecs / 128 thr
        const int i = c + v * BLK;
        if (i < CHUNK * 48) {
            const int st = i / 48, o = i % 48;
            long idx = (long)(t0 + st) * (N_GRID * 3) + (long)gb * 3 + o * 4;
            if (idx > limx) idx = limx;
            cp16(&s.sx[buf][st][o * 4], x_phy + idx);
        }
    }
    const long limd = (long)T_STEPS * N_GRID * 4 - 4;
    #pragma unroll
    for (int v = 0; v < 4; ++v) {                 // CHUNK*64 = 448 vecs / 128 thr
        const int i = c + v * BLK;
        if (i < CHUNK * 64) {
            const int st = i >> 6, o = i & 63;
            long idx = (long)(t0 + st) * (N_GRID * 4) + (long)gb * 4 + o * 4;
            if (idx > limd) idx = limd;
            cp16(&s.sd[buf][st][o * 4], pdy + idx);
        }
    }
}

// Per-thread HBV parameter set + routing weights + state
struct HbvState {
    float parFC, parK0, parK1, parK2, parPERC, parUZL, parTT,
          parCFMAX, parCWH, parC;
    float invFC, invLPFC, crf, gwcap;
    float snowpack, meltwater, sm, suz, slz;
    float w[LENF];
    float qh[LENF - 1];     // circular history, statically indexed
};

// One HBV step + inline 15-tap gamma-UH routing.
// RP = t mod 14 (compile-time) -> static ring indexing, zero register moves.
template<int RP>
__device__ __forceinline__ void step_body(
    HbvState& S, const Smem& sm_, int buf, int slot, int t,
    int lg, int m, int g, bool active, float* __restrict__ out)
{
    const float P  = sm_.sx[buf][slot][lg * 3 + 0];
    const float Ta = sm_.sx[buf][slot][lg * 3 + 1];
    const float PE = sm_.sx[buf][slot][lg * 3 + 2];
    const float beta   = sm_.sd[buf][slot][lg * 4 + m]     * 5.0f + 1.0f;
    const float betaet = sm_.sd[buf][slot][lg * 4 + 2 + m] * 4.7f + 0.3f;

    // --- snow bucket ---
    const float rain = (Ta >= S.parTT) ? P : 0.0f;
    const float snow = P - rain;
    S.snowpack += snow;
    const float melt = fminf(fmaxf(S.parCFMAX * (Ta - S.parTT), 0.0f), S.snowpack);
    S.meltwater += melt;
    S.snowpack  -= melt;
    const float refr = fminf(fmaxf(S.crf * (S.parTT - Ta), 0.0f), S.meltwater);
    S.snowpack  += refr;
    S.meltwater -= refr;
    const float tosoil = fmaxf(S.meltwater - S.parCWH * S.snowpack, 0.0f);
    S.meltwater -= tosoil;

    // --- soil bucket ---
    const float swet = fminf(__powf(S.sm * S.invFC, beta), 1.0f);
    const float rpt  = rain + tosoil;
    const float recharge = rpt * swet;
    S.sm += rpt - recharge;
    const float excess = fmaxf(S.sm - S.parFC, 0.0f);
    S.sm -= excess;
    const float efb = fminf(S.sm * S.invLPFC, 1.0f);
    const float ef  = __powf(efb, betaet);
    const float et  = fminf(S.sm, PE * ef);
    S.sm = fmaxf(S.sm - et, NEARZERO);
    const float cap = fminf(S.slz, S.parC * S.slz * (1.0f - fminf(S.sm * S.invFC, 1.0f)));
    S.sm  = fmaxf(S.sm + cap, NEARZERO);
    S.slz = fmaxf(S.slz - cap, NEARZERO);

    // --- groundwater buckets ---
    S.suz += recharge + excess;
    const float perc = fminf(S.suz, S.parPERC);
    S.suz -= perc;
    const float q0 = S.parK0 * fmaxf(S.suz - S.parUZL, 0.0f);
    S.suz -= q0;
    const float q1 = S.parK1 * S.suz;
    S.suz -= q1;
    S.slz += perc;
    const float gwl = fminf(S.slz, S.gwcap);
    S.slz -= gwl;
    const float q2 = S.parK2 * S.slz;
    S.slz -= q2;

    const float qt = q0 + q1 + q2;
    const float qs = 0.5f * (qt + __shfl_xor_sync(0xffffffffu, qt, 1));

    // --- routing: flow[t] = w0*q[t] + sum_{k=1..14} w[k]*q[t-k] ---
    float flow = S.w[0] * qs;
    #pragma unroll
    for (int k = 1; k < LENF; ++k)
        flow += S.w[k] * S.qh[(RP + 14 - k) % 14];
    S.qh[RP] = qs;

    if (active && m == 0 && t < T_STEPS) out[t * N_GRID + g] = flow;
}

__global__ void __launch_bounds__(BLK) hbv_fused(
    const float* __restrict__ x_phy,   // [T, G, 3]
    const float* __restrict__ ac_all,  // [G]
    const float* __restrict__ pdy,     // [T, G, 2, 2]
    const float* __restrict__ pstat,   // [G, 30]
    float* __restrict__ out)           // [T, G]
{
    __shared__ Smem smem;

    const int gb  = blockIdx.x * GPB;
    const int lg  = threadIdx.x >> 1;
    const int m   = threadIdx.x & 1;
    const int g   = gb + lg;
    const bool active = (g < N_GRID);
    const int gc  = active ? g : (N_GRID - 1);
    const int c   = threadIdx.x;

    // ---- static params ----
    const float* ps = pstat + gc * 30;
    HbvState S;
    S.parFC    = ps[0*2+m]  * 950.0f  + 50.0f;
    S.parK0    = ps[1*2+m]  * 0.85f   + 0.05f;
    S.parK1    = ps[2*2+m]  * 0.49f   + 0.01f;
    S.parK2    = ps[3*2+m]  * 0.199f  + 0.001f;
    const float parLP = ps[4*2+m] * 0.8f + 0.2f;
    S.parPERC  = ps[5*2+m]  * 10.0f;
    S.parUZL   = ps[6*2+m]  * 100.0f;
    S.parTT    = ps[7*2+m]  * 5.0f    - 2.5f;
    S.parCFMAX = ps[8*2+m]  * 9.5f    + 0.5f;
    const float parCFR = ps[9*2+m] * 0.1f;
    S.parCWH   = ps[10*2+m] * 0.2f;
    S.parC     = ps[11*2+m];
    const float parRT = ps[12*2+m] * 20.0f;
    const float parAC = ps[13*2+m] * 2500.0f;

    const float Ac = ac_all[gc];
    S.invFC   = 1.0f / S.parFC;
    S.invLPFC = 1.0f / (parLP * S.parFC);
    S.crf     = parCFR * S.parCFMAX;
    S.gwcap   = parRT * fminf(fmaxf(1.0f - Ac / (parAC + NEARZERO), 0.0f), 1.0f);

    // ---- normalized gamma-UH weights (lgamma & theta^-a cancel in normalization) ----
    const float a_r  = fmaxf(ps[28] * 2.9f, 0.0f) + 0.1f;
    const float th_r = fmaxf(ps[29] * 6.5f, 0.0f) + 0.5f;
    const float am1  = a_r - 1.0f;
    const float ivt  = 1.0f / th_r;
    const float LOGTK[LENF] = {
        -0.69314718f, 0.40546511f, 0.91629073f, 1.25276297f, 1.50407740f,
         1.70474809f, 1.87180218f, 2.01490302f, 2.14006616f, 2.25129180f,
         2.35137526f, 2.44234704f, 2.52572864f, 2.60268969f, 2.67414865f };
    float wsum = 0.0f;
    #pragma unroll
    for (int k = 0; k < LENF; ++k) {
        const float tk = (float)k + 0.5f;
        S.w[k] = __expf(am1 * LOGTK[k] - tk * ivt);
        wsum += S.w[k];
    }
    const float ivw = 1.0f / wsum;
    #pragma unroll
    for (int k = 0; k < LENF; ++k) S.w[k] *= ivw;

    // ---- state init ----
    S.snowpack = S.meltwater = S.sm = S.suz = S.slz = 1e-3f;
    #pragma unroll
    for (int k = 0; k < LENF - 1; ++k) S.qh[k] = 0.0f;

    // ---- pipeline prologue ----
    stage(smem, 0, 0,      gb, x_phy, pdy, c);
    asm volatile("cp.async.commit_group;\n");
    stage(smem, 1, CHUNK,  gb, x_phy, pdy, c);
    asm volatile("cp.async.commit_group;\n");

    // ---- 53 super-iterations x 14 steps ----
    for (int it = 0; it < 53; ++it) {
        const int t0 = it * 14;

        // ---------- phase A: consume buf0 (steps t0 .. t0+6) ----------
        asm volatile("cp.async.wait_group 1;\n");
        __syncthreads();
        step_body< 0>(S, smem, 0, 0, t0 + 0, lg, m, g, active, out);
        step_body< 1>(S, smem, 0, 1, t0 + 1, lg, m, g, active, out);
        step_body< 2>(S, smem, 0, 2, t0 + 2, lg, m, g, active, out);
        step_body< 3>(S, smem, 0, 3, t0 + 3, lg, m, g, active, out);
        step_body< 4>(S, smem, 0, 4, t0 + 4, lg, m, g, active, out);
        step_body< 5>(S, smem, 0, 5, t0 + 5, lg, m, g, active, out);
        step_body< 6>(S, smem, 0, 6, t0 + 6, lg, m, g, active, out);
        __syncthreads();
        {
            const int nch = it * 2 + 2;
            if (nch < NCHUNKS) stage(smem, 0, nch * CHUNK, gb, x_phy, pdy, c);
            asm volatile("cp.async.commit_group;\n");
        }

        // ---------- phase B: consume buf1 (steps t0+7 .. t0+13) ----------
        asm volatile("cp.async.wait_group 1;\n");
        __syncthreads();
        step_body< 7>(S, smem, 1, 0, t0 +  7, lg, m, g, active, out);
        step_body< 8>(S, smem, 1, 1, t0 +  8, lg, m, g, active, out);
        step_body< 9>(S, smem, 1, 2, t0 +  9, lg, m, g, active, out);
        step_body<10>(S, smem, 1, 3, t0 + 10, lg, m, g, active, out);
        step_body<11>(S, smem, 1, 4, t0 + 11, lg, m, g, active, out);
        step_body<12>(S, smem, 1, 5, t0 + 12, lg, m, g, active, out);
        step_body<13>(S, smem, 1, 6, t0 + 13, lg, m, g, active, out);
        __syncthreads();
        {
            const int nch = it * 2 + 3;
            if (nch < NCHUNKS) stage(smem, 1, nch * CHUNK, gb, x_phy, pdy, c);
            asm volatile("cp.async.commit_group;\n");
        }
    }
}

// ---------------------------------------------------------------------------
extern "C" void kernel_launch(void* const* d_in, const int* in_sizes, int n_in,
                              void* d_out, int out_size)
{
    const float* x_phy = (const float*)d_in[0];   // [730,10000,3]
    const float* ac    = (const float*)d_in[1];   // [10000]
    // d_in[2] = elev_all (unused by the model)
    const float* pdy   = (const float*)d_in[3];   // [730,10000,4]
    const float* pstat = (const float*)d_in[4];   // [10000,30]
    float* out = (float*)d_out;                   // [730,10000,1]

    hbv_fused<<<(2 * N_GRID + BLK - 1) / BLK, BLK>>>(x_phy, ac, pdy, pstat, out);
}